// round 7
// baseline (speedup 1.0000x reference)
#include <cuda_runtime.h>

// Pure HBM-streaming quadratic form:
//   total = sum over pairs (l1<=l2), weight w in {1,2}:
//           w * sum_s d1[s,:] . O[s,:,:] . d2[s,:],   d = c_in - c_tgt
// Overlap tensors: 356.5 MB read once -> memory-bound.
// R5: rectangular 16-row x 64-float4-col tiles (same 16KB units / 21760 blocks
//     as R3). Each thread owns ONE d2 column (loaded once, weight folded) and
//     4 rows -> 1 streamed LDG + 1 uniform scalar pair per iter, affine index
//     math, no prep kernel, no smem staging, single fused kernel.

#define TPB 256
#define NUNITS 21760

__device__ float    g_acc;   // zero-init at load; reset by last block each run
__device__ unsigned g_cnt;   // zero-init at load; reset by last block each run

struct Ptrs {
    const float4* o[10];     // ovlp pairs (0,0)(0,1)(0,2)(0,3)(1,1)(1,2)(1,3)(2,2)(2,3)(3,3)
    const float*  cin[4];    // c_in_l0..l3   (flattened [S, D_l])
    const float*  ctg[4];    // c_tgt_l0..l3
};

// One tile: 16 rows x 64 float4 cols of pair (D1, D2=4*C4), weight W.
// lt = local tile index within this pair. tid -> (col, row-quarter).
template <int D1, int C4, int W>
__device__ __forceinline__ float unit_acc(const float4* __restrict__ o,
                                          const float* __restrict__ in1, const float* __restrict__ tg1,
                                          const float4* __restrict__ in2, const float4* __restrict__ tg2,
                                          int lt, int tid) {
    constexpr int TR  = D1 / 16;     // row-tiles per structure
    constexpr int TC  = C4 / 64;     // col-tiles per structure
    constexpr int TPS = TR * TC;     // tiles per structure

    const int s   = lt / TPS;               // compile-time divisor
    const int rem = lt - s * TPS;
    const int tr  = rem / TC;                // compile-time divisor
    const int tc  = rem - tr * TC;

    const int col = tid & 63;
    const int rq  = tid >> 6;                // 0..3
    const int c4  = tc * 64 + col;
    const int r0  = tr * 16 + rq;            // this thread's first row; step 4

    // d2 column (float4), loaded once, weight folded
    const unsigned ci = (unsigned)s * C4 + c4;
    float4 a = in2[ci], b = tg2[ci];
    float4 d2 = make_float4((a.x - b.x) * (float)W, (a.y - b.y) * (float)W,
                            (a.z - b.z) * (float)W, (a.w - b.w) * (float)W);

    const float4* op = o + (unsigned)s * (D1 * C4) + (unsigned)r0 * C4 + c4;
    const float*  i1 = in1 + (unsigned)s * D1 + r0;
    const float*  t1 = tg1 + (unsigned)s * D1 + r0;

    float acc = 0.0f;
#pragma unroll
    for (int it = 0; it < 4; ++it) {
        float4 ov = __ldcs(op + it * 4 * C4);        // streamed, evict-first
        float  d1 = i1[it * 4] - t1[it * 4];         // warp-uniform, L1/L2 hit
        acc = fmaf(d1, ov.x * d2.x + ov.y * d2.y + ov.z * d2.z + ov.w * d2.w, acc);
    }
    return acc;
}

// Tile-count prefix sums (tile = 4096 floats), identical to R3:
// (0,0):128 (0,1):512 (0,2):1152 (0,3):2048 (1,1):3200
// (1,2):5120 (1,3):7808 (2,2):11008 (2,3):15488 (3,3):21760
__global__ void __launch_bounds__(TPB, 8) rho_kernel(Ptrs P, float* __restrict__ out) {
    const int b = blockIdx.x;
    const int tid = threadIdx.x;
    float acc;
    if      (b <   128) acc = unit_acc< 256,  64, 1>(P.o[0], P.cin[0], P.ctg[0], (const float4*)P.cin[0], (const float4*)P.ctg[0], b,         tid);
    else if (b <   512) acc = unit_acc< 256, 192, 2>(P.o[1], P.cin[0], P.ctg[0], (const float4*)P.cin[1], (const float4*)P.ctg[1], b -   128, tid);
    else if (b <  1152) acc = unit_acc< 256, 320, 2>(P.o[2], P.cin[0], P.ctg[0], (const float4*)P.cin[2], (const float4*)P.ctg[2], b -   512, tid);
    else if (b <  2048) acc = unit_acc< 256, 448, 2>(P.o[3], P.cin[0], P.ctg[0], (const float4*)P.cin[3], (const float4*)P.ctg[3], b -  1152, tid);
    else if (b <  3200) acc = unit_acc< 768, 192, 1>(P.o[4], P.cin[1], P.ctg[1], (const float4*)P.cin[1], (const float4*)P.ctg[1], b -  2048, tid);
    else if (b <  5120) acc = unit_acc< 768, 320, 2>(P.o[5], P.cin[1], P.ctg[1], (const float4*)P.cin[2], (const float4*)P.ctg[2], b -  3200, tid);
    else if (b <  7808) acc = unit_acc< 768, 448, 2>(P.o[6], P.cin[1], P.ctg[1], (const float4*)P.cin[3], (const float4*)P.ctg[3], b -  5120, tid);
    else if (b < 11008) acc = unit_acc<1280, 320, 1>(P.o[7], P.cin[2], P.ctg[2], (const float4*)P.cin[2], (const float4*)P.ctg[2], b -  7808, tid);
    else if (b < 15488) acc = unit_acc<1280, 448, 2>(P.o[8], P.cin[2], P.ctg[2], (const float4*)P.cin[3], (const float4*)P.ctg[3], b - 11008, tid);
    else                acc = unit_acc<1792, 448, 1>(P.o[9], P.cin[3], P.ctg[3], (const float4*)P.cin[3], (const float4*)P.ctg[3], b - 15488, tid);

    // warp reduce
#pragma unroll
    for (int off = 16; off > 0; off >>= 1)
        acc += __shfl_down_sync(0xffffffffu, acc, off);

    __shared__ float ws[TPB / 32];
    if ((tid & 31) == 0) ws[tid >> 5] = acc;
    __syncthreads();
    if (tid == 0) {
        float s = ws[0];
#pragma unroll
        for (int w = 1; w < TPB / 32; ++w) s += ws[w];
        atomicAdd(&g_acc, s);
        __threadfence();
        unsigned old = atomicAdd(&g_cnt, 1u);
        if (old == NUNITS - 1) {
            float v = atomicExch(&g_acc, 0.0f);   // drain + reset for next replay
            out[0] = v;
            atomicExch(&g_cnt, 0u);               // reset counter for next replay
        }
    }
}

extern "C" void kernel_launch(void* const* d_in, const int* in_sizes, int n_in,
                              void* d_out, int out_size) {
    (void)in_sizes; (void)n_in; (void)out_size;
    Ptrs P;
    // inputs: c_in_l0, c_tgt_l0, ..., c_in_l3, c_tgt_l3, then 10 ovlp blocks
    for (int l = 0; l < 4; ++l) {
        P.cin[l] = (const float*)d_in[2 * l];
        P.ctg[l] = (const float*)d_in[2 * l + 1];
    }
    for (int k = 0; k < 10; ++k) P.o[k] = (const float4*)d_in[8 + k];

    rho_kernel<<<NUNITS, TPB>>>(P, (float*)d_out);
}

// round 8
// speedup vs baseline: 1.1793x; 1.1793x over previous
#include <cuda_runtime.h>

// Pure HBM-streaming quadratic form:
//   total = sum over pairs (l1<=l2), weight w in {1,2}:
//           w * sum_s d1[s,:] . O[s,:,:] . d2[s,:],   d = c_in - c_tgt
// Overlap tensors: 356.5 MB read once -> memory-bound.
// R5: rectangular 16-row x 64-float4-col tiles (same 16KB units / 21760 blocks
//     as R3). Each thread owns ONE d2 column (loaded once, weight folded) and
//     4 rows -> 1 streamed LDG + 1 uniform scalar pair per iter, affine index
//     math, no prep kernel, no smem staging, single fused kernel.

#define TPB 256
#define NUNITS 21760

__device__ float    g_acc;   // zero-init at load; reset by last block each run
__device__ unsigned g_cnt;   // zero-init at load; reset by last block each run

struct Ptrs {
    const float4* o[10];     // ovlp pairs (0,0)(0,1)(0,2)(0,3)(1,1)(1,2)(1,3)(2,2)(2,3)(3,3)
    const float*  cin[4];    // c_in_l0..l3   (flattened [S, D_l])
    const float*  ctg[4];    // c_tgt_l0..l3
};

// One tile: 16 rows x 64 float4 cols of pair (D1, D2=4*C4), weight W.
// lt = local tile index within this pair. tid -> (col, row-quarter).
template <int D1, int C4, int W>
__device__ __forceinline__ float unit_acc(const float4* __restrict__ o,
                                          const float* __restrict__ in1, const float* __restrict__ tg1,
                                          const float4* __restrict__ in2, const float4* __restrict__ tg2,
                                          int lt, int tid) {
    constexpr int TR  = D1 / 16;     // row-tiles per structure
    constexpr int TC  = C4 / 64;     // col-tiles per structure
    constexpr int TPS = TR * TC;     // tiles per structure

    const int s   = lt / TPS;               // compile-time divisor
    const int rem = lt - s * TPS;
    const int tr  = rem / TC;                // compile-time divisor
    const int tc  = rem - tr * TC;

    const int col = tid & 63;
    const int rq  = tid >> 6;                // 0..3
    const int c4  = tc * 64 + col;
    const int r0  = tr * 16 + rq;            // this thread's first row; step 4

    // d2 column (float4), loaded once, weight folded
    const unsigned ci = (unsigned)s * C4 + c4;
    float4 a = in2[ci], b = tg2[ci];
    float4 d2 = make_float4((a.x - b.x) * (float)W, (a.y - b.y) * (float)W,
                            (a.z - b.z) * (float)W, (a.w - b.w) * (float)W);

    const float4* op = o + (unsigned)s * (D1 * C4) + (unsigned)r0 * C4 + c4;
    const float*  i1 = in1 + (unsigned)s * D1 + r0;
    const float*  t1 = tg1 + (unsigned)s * D1 + r0;

    float acc = 0.0f;
#pragma unroll
    for (int it = 0; it < 4; ++it) {
        float4 ov = __ldcs(op + it * 4 * C4);        // streamed, evict-first
        float  d1 = i1[it * 4] - t1[it * 4];         // warp-uniform, L1/L2 hit
        acc = fmaf(d1, ov.x * d2.x + ov.y * d2.y + ov.z * d2.z + ov.w * d2.w, acc);
    }
    return acc;
}

// Tile-count prefix sums (tile = 4096 floats), identical to R3:
// (0,0):128 (0,1):512 (0,2):1152 (0,3):2048 (1,1):3200
// (1,2):5120 (1,3):7808 (2,2):11008 (2,3):15488 (3,3):21760
__global__ void __launch_bounds__(TPB, 8) rho_kernel(Ptrs P, float* __restrict__ out) {
    const int b = blockIdx.x;
    const int tid = threadIdx.x;
    float acc;
    if      (b <   128) acc = unit_acc< 256,  64, 1>(P.o[0], P.cin[0], P.ctg[0], (const float4*)P.cin[0], (const float4*)P.ctg[0], b,         tid);
    else if (b <   512) acc = unit_acc< 256, 192, 2>(P.o[1], P.cin[0], P.ctg[0], (const float4*)P.cin[1], (const float4*)P.ctg[1], b -   128, tid);
    else if (b <  1152) acc = unit_acc< 256, 320, 2>(P.o[2], P.cin[0], P.ctg[0], (const float4*)P.cin[2], (const float4*)P.ctg[2], b -   512, tid);
    else if (b <  2048) acc = unit_acc< 256, 448, 2>(P.o[3], P.cin[0], P.ctg[0], (const float4*)P.cin[3], (const float4*)P.ctg[3], b -  1152, tid);
    else if (b <  3200) acc = unit_acc< 768, 192, 1>(P.o[4], P.cin[1], P.ctg[1], (const float4*)P.cin[1], (const float4*)P.ctg[1], b -  2048, tid);
    else if (b <  5120) acc = unit_acc< 768, 320, 2>(P.o[5], P.cin[1], P.ctg[1], (const float4*)P.cin[2], (const float4*)P.ctg[2], b -  3200, tid);
    else if (b <  7808) acc = unit_acc< 768, 448, 2>(P.o[6], P.cin[1], P.ctg[1], (const float4*)P.cin[3], (const float4*)P.ctg[3], b -  5120, tid);
    else if (b < 11008) acc = unit_acc<1280, 320, 1>(P.o[7], P.cin[2], P.ctg[2], (const float4*)P.cin[2], (const float4*)P.ctg[2], b -  7808, tid);
    else if (b < 15488) acc = unit_acc<1280, 448, 2>(P.o[8], P.cin[2], P.ctg[2], (const float4*)P.cin[3], (const float4*)P.ctg[3], b - 11008, tid);
    else                acc = unit_acc<1792, 448, 1>(P.o[9], P.cin[3], P.ctg[3], (const float4*)P.cin[3], (const float4*)P.ctg[3], b - 15488, tid);

    // warp reduce
#pragma unroll
    for (int off = 16; off > 0; off >>= 1)
        acc += __shfl_down_sync(0xffffffffu, acc, off);

    __shared__ float ws[TPB / 32];
    if ((tid & 31) == 0) ws[tid >> 5] = acc;
    __syncthreads();
    if (tid == 0) {
        float s = ws[0];
#pragma unroll
        for (int w = 1; w < TPB / 32; ++w) s += ws[w];
        atomicAdd(&g_acc, s);
        __threadfence();
        unsigned old = atomicAdd(&g_cnt, 1u);
        if (old == NUNITS - 1) {
            float v = atomicExch(&g_acc, 0.0f);   // drain + reset for next replay
            out[0] = v;
            atomicExch(&g_cnt, 0u);               // reset counter for next replay
        }
    }
}

extern "C" void kernel_launch(void* const* d_in, const int* in_sizes, int n_in,
                              void* d_out, int out_size) {
    (void)in_sizes; (void)n_in; (void)out_size;
    Ptrs P;
    // inputs: c_in_l0, c_tgt_l0, ..., c_in_l3, c_tgt_l3, then 10 ovlp blocks
    for (int l = 0; l < 4; ++l) {
        P.cin[l] = (const float*)d_in[2 * l];
        P.ctg[l] = (const float*)d_in[2 * l + 1];
    }
    for (int k = 0; k < 10; ++k) P.o[k] = (const float4*)d_in[8 + k];

    rho_kernel<<<NUNITS, TPB>>>(P, (float*)d_out);
}

// round 9
// speedup vs baseline: 1.2080x; 1.0244x over previous
#include <cuda_runtime.h>

// Pure HBM-streaming quadratic form:
//   total = sum over pairs (l1<=l2), weight w in {1,2}:
//           w * sum_s d1[s,:] . O[s,:,:] . d2[s,:],   d = c_in - c_tgt
// Overlap tensors: 356.5 MB read once -> memory-bound.
// R9 = R3 (best: linear per-block 16KB streams, 21760 blocks, IT=4, 8 CTAs/SM)
//      + weight hoisted out of inner loop (once per block)
//      + __ldg for the d vectors (L1-resident, no L2 competition with stream).

#define TPB 256
#define IT  4                 // float4 per thread; unit = TPB*IT*4 = 4096 floats
#define NUNITS 21760          // total blocks

// delta coefficients, concatenated by l:
//   l0: [0,2048), l1: [2048,8192), l2: [8192,18432), l3: [18432,32768)
__device__ __align__(16) float g_d[32768];

__global__ void prep_kernel(const float* __restrict__ i0, const float* __restrict__ t0,
                            const float* __restrict__ i1, const float* __restrict__ t1,
                            const float* __restrict__ i2, const float* __restrict__ t2,
                            const float* __restrict__ i3, const float* __restrict__ t3,
                            float* out) {
    int idx = blockIdx.x * blockDim.x + threadIdx.x;
    if (idx == 0) out[0] = 0.0f;
    if (idx < 2048) {
        g_d[idx] = i0[idx] - t0[idx];
    } else if (idx < 8192) {
        int j = idx - 2048;  g_d[idx] = i1[j] - t1[j];
    } else if (idx < 18432) {
        int j = idx - 8192;  g_d[idx] = i2[j] - t2[j];
    } else if (idx < 32768) {
        int j = idx - 18432; g_d[idx] = i3[j] - t3[j];
    }
}

struct OvlpPtrs { const float4* p[10]; };

// One unit of one pair. D1/D2 compile-time -> div/mod become mul-shift.
// lu = local unit index within this pair's range. Weight applied ONCE at end.
template <int D1, int D2, int W, int OFF1, int OFF2>
__device__ __forceinline__ float unit_acc(const float4* __restrict__ o, int lu, int tid) {
    constexpr unsigned C4 = D2 / 4;  // float4 columns; >= 64 so a warp shares one row r
    float acc = 0.0f;
    unsigned base = (unsigned)lu * (TPB * IT) + tid;
#pragma unroll
    for (int it = 0; it < IT; ++it) {
        unsigned idx4 = base + (unsigned)it * TPB;
        unsigned c4 = idx4 % C4;
        unsigned rs = idx4 / C4;
        unsigned r  = rs % (unsigned)D1;
        unsigned s  = rs / (unsigned)D1;
        float4 ov = __ldcs(&o[idx4]);                                   // streamed, evict-first
        const float4 d2 = __ldg((const float4*)&g_d[OFF2 + s * D2 + c4 * 4]); // L1-resident
        float d1 = __ldg(&g_d[OFF1 + s * D1 + r]);                      // warp-uniform broadcast
        acc = fmaf(d1, ov.x * d2.x + ov.y * d2.y + ov.z * d2.z + ov.w * d2.w, acc);
    }
    return (W == 2) ? (acc + acc) : acc;   // weight once per block
}

// Unit-count prefix sums per pair (each unit = TPB*IT float4 = 4096 floats):
// (0,0):128  (0,1):384  (0,2):640  (0,3):896  (1,1):1152
// (1,2):1920 (1,3):2688 (2,2):3200 (2,3):4480 (3,3):6272  total = 21760
__global__ void __launch_bounds__(TPB, 8) rho_kernel(OvlpPtrs o, float* __restrict__ out) {
    int b = blockIdx.x;
    int tid = threadIdx.x;
    float acc;
    if      (b <   128) acc = unit_acc< 256,  256, 1,     0,     0>(o.p[0], b,         tid);
    else if (b <   512) acc = unit_acc< 256,  768, 2,     0,  2048>(o.p[1], b -   128, tid);
    else if (b <  1152) acc = unit_acc< 256, 1280, 2,     0,  8192>(o.p[2], b -   512, tid);
    else if (b <  2048) acc = unit_acc< 256, 1792, 2,     0, 18432>(o.p[3], b -  1152, tid);
    else if (b <  3200) acc = unit_acc< 768,  768, 1,  2048,  2048>(o.p[4], b -  2048, tid);
    else if (b <  5120) acc = unit_acc< 768, 1280, 2,  2048,  8192>(o.p[5], b -  3200, tid);
    else if (b <  7808) acc = unit_acc< 768, 1792, 2,  2048, 18432>(o.p[6], b -  5120, tid);
    else if (b < 11008) acc = unit_acc<1280, 1280, 1,  8192,  8192>(o.p[7], b -  7808, tid);
    else if (b < 15488) acc = unit_acc<1280, 1792, 2,  8192, 18432>(o.p[8], b - 11008, tid);
    else                acc = unit_acc<1792, 1792, 1, 18432, 18432>(o.p[9], b - 15488, tid);

    // warp reduce
#pragma unroll
    for (int off = 16; off > 0; off >>= 1)
        acc += __shfl_down_sync(0xffffffffu, acc, off);

    __shared__ float ws[TPB / 32];
    if ((tid & 31) == 0) ws[tid >> 5] = acc;
    __syncthreads();
    if (tid == 0) {
        float s = ws[0];
#pragma unroll
        for (int w = 1; w < TPB / 32; ++w) s += ws[w];
        atomicAdd(out, s);
    }
}

extern "C" void kernel_launch(void* const* d_in, const int* in_sizes, int n_in,
                              void* d_out, int out_size) {
    (void)in_sizes; (void)n_in; (void)out_size;
    const float* i0 = (const float*)d_in[0];
    const float* t0 = (const float*)d_in[1];
    const float* i1 = (const float*)d_in[2];
    const float* t1 = (const float*)d_in[3];
    const float* i2 = (const float*)d_in[4];
    const float* t2 = (const float*)d_in[5];
    const float* i3 = (const float*)d_in[6];
    const float* t3 = (const float*)d_in[7];

    OvlpPtrs o;
    for (int k = 0; k < 10; ++k) o.p[k] = (const float4*)d_in[8 + k];

    float* out = (float*)d_out;
    prep_kernel<<<128, TPB>>>(i0, t0, i1, t1, i2, t2, i3, t3, out);
    rho_kernel<<<NUNITS, TPB>>>(o, out);
}